// round 4
// baseline (speedup 1.0000x reference)
#include <cuda_runtime.h>
#include <cstdint>

// Fixed problem shape: Q=4096, N=65536, D=128, K_TOP=21.
#define D_DIM 128
#define K_TOP 21
#define TILE  128     // n-tile and q-tile
#define KCH   16      // K chunk

// Monotonic map fp32 -> u32 (order-preserving, total order).
__device__ __forceinline__ unsigned fp32_ord(float f) {
    unsigned u = __float_as_uint(f);
    return u ^ (((int)u >> 31) | 0x80000000u);
}

// ---------------------------------------------------------------------------
// Fused kernel: for a block of 128 database rows n, stream over all Q queries
// in 128-wide tiles; compute fp32 scores S[n][q] = dot(xb[n], xq[q]) and
// maintain per-n running top-21 as sorted (value desc, index asc) 64-bit keys.
// No global scratch. Output indices are written AS FLOAT32 VALUES.
// ---------------------------------------------------------------------------
__global__ __launch_bounds__(256) void fused_gemm_topk_kernel(
    const float* __restrict__ xq,   // [Q, 128]
    const float* __restrict__ xb,   // [N, 128]
    int Q, int N, float* __restrict__ out)   // out [21, N] (float-encoded idx)
{
    __shared__ float sA[KCH][TILE + 4];            // xq^T chunk: sA[k][q]
    __shared__ float sB[KCH][TILE + 4];            // xb^T chunk: sB[k][n]
    __shared__ unsigned long long lists[TILE][K_TOP]; // per-n sorted keys, desc
    __shared__ unsigned thresh[TILE];              // ord of current 21st value

    const int tid = threadIdx.x;
    const int tx  = tid & 15;        // q-direction microtile
    const int ty  = tid >> 4;        // n-direction microtile (half-warp id)
    const int n0  = blockIdx.x * TILE;
    const int halfsel = ty & 1;
    const unsigned hmask = 0xFFFFu << (halfsel * 16);

    // Init top-k state. Key 0 never collides with a real key (ord==0 would
    // require the fp32 bit pattern 0xFFFFFFFF = -NaN, impossible here).
    for (int i = tid; i < TILE * K_TOP; i += 256)
        ((unsigned long long*)lists)[i] = 0ull;
    for (int i = tid; i < TILE; i += 256) thresh[i] = 0u;
    __syncthreads();

    for (int q0 = 0; q0 < Q; q0 += TILE) {
        // ---------------- GEMM tile: 128n x 128q, K=128 ----------------
        float acc[8][8];
#pragma unroll
        for (int i = 0; i < 8; i++)
#pragma unroll
            for (int j = 0; j < 8; j++) acc[i][j] = 0.f;

        for (int k0 = 0; k0 < D_DIM; k0 += KCH) {
            // Load 128x16 chunks of xq and xb transposed into smem.
            // 2048 floats each = 512 float4; 256 threads x 2 float4.
#pragma unroll
            for (int i = 0; i < 2; i++) {
                int idx = tid + i * 256;        // 0..511
                int r   = idx >> 2;             // 0..127
                int c4  = (idx & 3) << 2;       // 0,4,8,12
                float4 a = *(const float4*)(xq + (size_t)(q0 + r) * D_DIM + k0 + c4);
                sA[c4 + 0][r] = a.x; sA[c4 + 1][r] = a.y;
                sA[c4 + 2][r] = a.z; sA[c4 + 3][r] = a.w;
                float4 b = *(const float4*)(xb + (size_t)(n0 + r) * D_DIM + k0 + c4);
                sB[c4 + 0][r] = b.x; sB[c4 + 1][r] = b.y;
                sB[c4 + 2][r] = b.z; sB[c4 + 3][r] = b.w;
            }
            __syncthreads();

#pragma unroll
            for (int k = 0; k < KCH; k++) {
                float a[8], b[8];
                *(float4*)&a[0] = *(const float4*)&sA[k][tx * 8];
                *(float4*)&a[4] = *(const float4*)&sA[k][tx * 8 + 4];
                *(float4*)&b[0] = *(const float4*)&sB[k][ty * 8];
                *(float4*)&b[4] = *(const float4*)&sB[k][ty * 8 + 4];
#pragma unroll
                for (int i = 0; i < 8; i++)
#pragma unroll
                    for (int j = 0; j < 8; j++)
                        acc[i][j] = fmaf(b[i], a[j], acc[i][j]);
            }
            __syncthreads();
        }

        // ---------------- Top-k update ----------------
        // Half-warp (ty) exclusively owns rows n0 + ty*8 .. +7; thread tx
        // holds that row's q values q0 + tx*8 .. +7 in acc[i][*].
#pragma unroll
        for (int i = 0; i < 8; i++) {
            int row = ty * 8 + i;
            unsigned th = thresh[row];           // possibly stale-low: safe
            unsigned ov[8];
            bool any = false;
#pragma unroll
            for (int j = 0; j < 8; j++) {
                ov[j] = fp32_ord(acc[i][j]);
                any |= (ov[j] >= th);
            }
            unsigned bal = __ballot_sync(hmask, any);
            unsigned qm  = (bal >> (halfsel * 16)) & 0xFFFFu;
            while (qm) {
                int t = __ffs(qm) - 1;
                qm &= qm - 1;
                if (tx == t) {
                    unsigned long long* L = lists[row];
#pragma unroll
                    for (int j = 0; j < 8; j++) {
                        unsigned long long key =
                            ((unsigned long long)ov[j] << 32) |
                            (unsigned long long)(0xFFFFFFFFu - (unsigned)(q0 + tx * 8 + j));
                        if (key > L[K_TOP - 1]) {
                            int p = K_TOP - 1;
                            while (p > 0 && L[p - 1] < key) { L[p] = L[p - 1]; p--; }
                            L[p] = key;
                        }
                    }
                    thresh[row] = (unsigned)(lists[row][K_TOP - 1] >> 32);
                }
                __syncwarp(hmask);
            }
        }
        // sA/sB for the next tile are rewritten before the next __syncthreads;
        // topk only touches acc + this half-warp's private lists — no hazard.
    }

    __syncthreads();
    // Emit: out[k][n], lists sorted by (value desc, index asc).
    // Indices are emitted as FLOAT32 values (harness output dtype is fp32);
    // 0..4095 are exactly representable.
    for (int e = tid; e < TILE * K_TOP; e += 256) {
        int row = e / K_TOP;
        int k   = e % K_TOP;
        unsigned idx = 0xFFFFFFFFu - (unsigned)(lists[row][k] & 0xFFFFFFFFull);
        out[(size_t)k * N + (n0 + row)] = (float)idx;
    }
}

// ---------------------------------------------------------------------------
// Launch. Inputs bound BY SIZE: N comes from out_size (out is [21, N]); the
// input with N*128 elements is xb (database), the other is xq (queries).
// ---------------------------------------------------------------------------
extern "C" void kernel_launch(void* const* d_in, const int* in_sizes, int n_in,
                              void* d_out, int out_size)
{
    float* out = (float*)d_out;

    const int N = out_size / K_TOP;
    const float* xq;
    const float* xb;
    int Q;

    if (in_sizes[0] == N * D_DIM && in_sizes[1] != N * D_DIM) {
        xb = (const float*)d_in[0];
        xq = (const float*)d_in[1];
        Q  = in_sizes[1] / D_DIM;
    } else {
        xq = (const float*)d_in[0];
        xb = (const float*)d_in[1];
        Q  = in_sizes[0] / D_DIM;
    }

    fused_gemm_topk_kernel<<<N / TILE, 256>>>(xq, xb, Q, N, out);
}

// round 5
// speedup vs baseline: 1.2991x; 1.2991x over previous
#include <cuda_runtime.h>
#include <cstdint>

// Fixed problem shape: Q=4096, N=65536, D=128, K_TOP=21.
#define D_DIM 128
#define K_TOP 21
#define TILE  128          // n-tile (per CTA) and q-tile
#define KCH   32           // xq k-chunk per cp.async stage
#define SB_STRIDE 132      // padded row stride (floats); 132*4 % 16 == 0
#define SB_WORDS (D_DIM * SB_STRIDE)   // xb tile: 128 k-rows
#define SA_WORDS (KCH * SB_STRIDE)     // one xq chunk buffer

// Monotonic map fp32 -> u32 (order-preserving, total order).
__device__ __forceinline__ unsigned fp32_ord(float f) {
    unsigned u = __float_as_uint(f);
    return u ^ (((int)u >> 31) | 0x80000000u);
}

// Async-copy one 32k x 128q chunk of xq, transposed, into dstbuf[k][q].
__device__ __forceinline__ void load_chunk_async(
    float* dstbuf, const float* __restrict__ xq, int q0, int kc, int tid)
{
#pragma unroll
    for (int i = 0; i < 16; i++) {
        int f  = i * 256 + tid;          // 0..4095
        int kl = f & 31;                 // k within chunk
        int q  = f >> 5;                 // q within tile (warp: fixed q, k 0..31 -> coalesced)
        const float* g = xq + (size_t)(q0 + q) * D_DIM + kc + kl;
        unsigned saddr = (unsigned)__cvta_generic_to_shared(dstbuf + kl * SB_STRIDE + q);
        asm volatile("cp.async.ca.shared.global [%0], [%1], 4;\n" :: "r"(saddr), "l"(g));
    }
    asm volatile("cp.async.commit_group;\n" ::: "memory");
}

// ---------------------------------------------------------------------------
// Fused GEMM + top-21. CTA owns 128 database rows (xb resident in smem for
// the whole kernel); xq streams through double-buffered cp.async chunks.
// Accumulation: single fp32 accumulator per (n,q), k ascending (bit-stable
// vs the reference — do not change).
// ---------------------------------------------------------------------------
__global__ __launch_bounds__(256, 1) void fused_gemm_topk_kernel(
    const float* __restrict__ xq,   // [Q, 128]
    const float* __restrict__ xb,   // [N, 128]
    int Q, int N, float* __restrict__ out)   // out [21, N] (float-encoded idx)
{
    extern __shared__ float smem[];
    float* sB  = smem;                       // [128][132]  xb^T (k-major)
    float* sA0 = smem + SB_WORDS;            // [32][132]   xq chunk buf 0
    float* sA1 = sA0 + SA_WORDS;             // [32][132]   xq chunk buf 1
    unsigned long long* lists = (unsigned long long*)(sA1 + SA_WORDS); // [128][21]
    unsigned* thresh = (unsigned*)(lists + TILE * K_TOP);              // [128]

    const int tid = threadIdx.x;
    const int tx  = tid & 15;        // q microtile
    const int ty  = tid >> 4;        // n microtile (half-warp id)
    const int n0  = blockIdx.x * TILE;
    const int halfsel = ty & 1;
    const unsigned hmask = 0xFFFFu << (halfsel * 16);

    // Init top-k state (key 0 can't collide with any real key).
    for (int i = tid; i < TILE * K_TOP; i += 256) lists[i] = 0ull;
    for (int i = tid; i < TILE; i += 256) thresh[i] = 0u;

    // Load this CTA's xb tile once, transposed: sB[k][n].
#pragma unroll
    for (int i = 0; i < 16; i++) {
        int idx = i * 256 + tid;          // 0..4095 float4s
        int r   = idx >> 5;               // n row 0..127
        int c4  = (idx & 31) << 2;        // k 0,4,...,124
        float4 b = *(const float4*)(xb + (size_t)(n0 + r) * D_DIM + c4);
        sB[(c4 + 0) * SB_STRIDE + r] = b.x;
        sB[(c4 + 1) * SB_STRIDE + r] = b.y;
        sB[(c4 + 2) * SB_STRIDE + r] = b.z;
        sB[(c4 + 3) * SB_STRIDE + r] = b.w;
    }

    const int nTiles = Q / TILE;
    const int cTotal = nTiles * (D_DIM / KCH);

    // Prologue: kick off chunk 0.
    load_chunk_async(sA0, xq, 0, 0, tid);

    int ct = 0;
    for (int tile = 0; tile < nTiles; tile++) {
        const int q0 = tile * TILE;

        float acc[8][8];
#pragma unroll
        for (int i = 0; i < 8; i++)
#pragma unroll
            for (int j = 0; j < 8; j++) acc[i][j] = 0.f;

        for (int c = 0; c < D_DIM / KCH; c++, ct++) {
            __syncthreads();   // close compute on the other buffer (and topk/init)

            if (ct + 1 < cTotal) {
                int nct = ct + 1;
                load_chunk_async((nct & 1) ? sA1 : sA0, xq,
                                 (nct >> 2) * TILE, (nct & 3) * KCH, tid);
                asm volatile("cp.async.wait_group 1;\n" ::: "memory");
            } else {
                asm volatile("cp.async.wait_group 0;\n" ::: "memory");
            }
            __syncthreads();   // chunk ct visible to all

            const float* A = (ct & 1) ? sA1 : sA0;
            const float* Bc = sB + c * KCH * SB_STRIDE;
#pragma unroll 8
            for (int k = 0; k < KCH; k++) {
                float a[8], bb[8];
                const float* Ak = A  + k * SB_STRIDE;
                const float* Bk = Bc + k * SB_STRIDE;
                *(float4*)&a[0]  = *(const float4*)(Ak + tx * 8);
                *(float4*)&a[4]  = *(const float4*)(Ak + tx * 8 + 4);
                *(float4*)&bb[0] = *(const float4*)(Bk + ty * 8);
                *(float4*)&bb[4] = *(const float4*)(Bk + ty * 8 + 4);
#pragma unroll
                for (int i = 0; i < 8; i++)
#pragma unroll
                    for (int j = 0; j < 8; j++)
                        acc[i][j] = fmaf(bb[i], a[j], acc[i][j]);
            }
        }

        // ---------------- Top-k update ----------------
        // Half-warp ty exclusively owns rows n0 + ty*8 .. +7; thread tx holds
        // q values q0 + tx*8 .. +7 for those rows in acc[i][*].
#pragma unroll
        for (int i = 0; i < 8; i++) {
            int row = ty * 8 + i;
            unsigned th = thresh[row];     // possibly stale-low: safe
            unsigned ov[8];
            bool any = false;
#pragma unroll
            for (int j = 0; j < 8; j++) {
                ov[j] = fp32_ord(acc[i][j]);
                any |= (ov[j] >= th);
            }
            unsigned bal = __ballot_sync(hmask, any);
            unsigned qm  = (bal >> (halfsel * 16)) & 0xFFFFu;
            while (qm) {
                int t = __ffs(qm) - 1;
                qm &= qm - 1;
                if (tx == t) {
                    unsigned long long* L = lists + (size_t)row * K_TOP;
#pragma unroll
                    for (int j = 0; j < 8; j++) {
                        unsigned long long key =
                            ((unsigned long long)ov[j] << 32) |
                            (unsigned long long)(0xFFFFFFFFu - (unsigned)(q0 + tx * 8 + j));
                        if (key > L[K_TOP - 1]) {
                            int p = K_TOP - 1;
                            while (p > 0 && L[p - 1] < key) { L[p] = L[p - 1]; p--; }
                            L[p] = key;
                        }
                    }
                    thresh[row] = (unsigned)(L[K_TOP - 1] >> 32);
                }
                __syncwarp(hmask);
            }
        }
        // lists/thresh writes are closed by the __syncthreads at the top of
        // the next chunk iteration (or the one below, after the last tile).
    }

    __syncthreads();
    // Emit: out[k][n] as FLOAT32 values (0..4095 exactly representable).
    for (int e = tid; e < TILE * K_TOP; e += 256) {
        int row = e / K_TOP;
        int k   = e % K_TOP;
        unsigned idx = 0xFFFFFFFFu -
            (unsigned)(lists[(size_t)row * K_TOP + k] & 0xFFFFFFFFull);
        out[(size_t)k * N + (n0 + row)] = (float)idx;
    }
}

// ---------------------------------------------------------------------------
// Launch. Inputs bound BY SIZE: N comes from out_size (out is [21, N]); the
// input with N*128 elements is xb (database), the other is xq (queries).
// ---------------------------------------------------------------------------
extern "C" void kernel_launch(void* const* d_in, const int* in_sizes, int n_in,
                              void* d_out, int out_size)
{
    float* out = (float*)d_out;

    const int N = out_size / K_TOP;
    const float* xq;
    const float* xb;
    int Q;

    if (in_sizes[0] == N * D_DIM && in_sizes[1] != N * D_DIM) {
        xb = (const float*)d_in[0];
        xq = (const float*)d_in[1];
        Q  = in_sizes[1] / D_DIM;
    } else {
        xq = (const float*)d_in[0];
        xb = (const float*)d_in[1];
        Q  = in_sizes[0] / D_DIM;
    }

    const int smem_bytes = (SB_WORDS + 2 * SA_WORDS) * 4
                         + TILE * K_TOP * 8 + TILE * 4;   // ~123.4 KB
    cudaFuncSetAttribute(fused_gemm_topk_kernel,
                         cudaFuncAttributeMaxDynamicSharedMemorySize, smem_bytes);

    fused_gemm_topk_kernel<<<N / TILE, 256, smem_bytes>>>(xq, xb, Q, N, out);
}

// round 6
// speedup vs baseline: 2.7203x; 2.0940x over previous
#include <cuda_runtime.h>
#include <cstdint>

// Fixed problem shape: Q=4096, N=65536, D=128, K_TOP=21.
#define D_DIM 128
#define K_TOP 21
#define TILE  128          // n-tile (per CTA) and q-tile
#define KCH   32           // xq k-chunk per cp.async stage
#define NSTAGE 3           // cp.async ring depth
#define SA_STRIDE 132      // padded row stride (floats), 16B-aligned rows
#define SB_STRIDE 132
#define SB_WORDS (D_DIM * SB_STRIDE)
#define SA_WORDS (KCH * SA_STRIDE)
#define NTHREADS 512

// Monotonic map fp32 -> u32 (order-preserving, total order).
__device__ __forceinline__ unsigned fp32_ord(float f) {
    unsigned u = __float_as_uint(f);
    return u ^ (((int)u >> 31) | 0x80000000u);
}

// Async-copy one 32k x 128q chunk of xq, transposed, into dstbuf[k][q].
// lane -> k (global 128B-coalesced), f>>5 -> q.
__device__ __forceinline__ void load_chunk_async(
    float* dstbuf, const float* __restrict__ xq, int q0, int kc, int tid)
{
#pragma unroll
    for (int i = 0; i < 8; i++) {
        int f  = i * NTHREADS + tid;     // 0..4095
        int kl = f & 31;                 // k within chunk (= lane)
        int q  = f >> 5;                 // q within tile
        const float* g = xq + (size_t)(q0 + q) * D_DIM + kc + kl;
        unsigned saddr = (unsigned)__cvta_generic_to_shared(dstbuf + kl * SA_STRIDE + q);
        asm volatile("cp.async.ca.shared.global [%0], [%1], 4;\n" :: "r"(saddr), "l"(g));
    }
    asm volatile("cp.async.commit_group;\n" ::: "memory");
}

// ---------------------------------------------------------------------------
// Fused GEMM + top-21. CTA owns 128 database rows (xb resident in smem);
// xq streams through a 3-stage cp.async ring. 512 threads, 8n x 4q microtile.
// Accumulation: single fp32 accumulator per (n,q), k ascending (bit-stable
// vs the reference — do not change).
// ---------------------------------------------------------------------------
__global__ __launch_bounds__(NTHREADS, 1) void fused_gemm_topk_kernel(
    const float* __restrict__ xq,   // [Q, 128]
    const float* __restrict__ xb,   // [N, 128]
    int Q, int N, float* __restrict__ out)   // out [21, N] (float-encoded idx)
{
    extern __shared__ float smem[];
    float* sB = smem;                        // [128][132]  xb^T (k-major)
    float* sA = smem + SB_WORDS;             // [3][32][132] xq ring
    unsigned long long* lists = (unsigned long long*)(sA + NSTAGE * SA_WORDS); // [128][21]
    unsigned* thresh = (unsigned*)(lists + TILE * K_TOP);                      // [128]

    const int tid  = threadIdx.x;
    const int lane = tid & 31;
    const int tx   = tid & 31;       // q microtile: 4 consecutive q per thread
    const int ty   = tid >> 5;       // warp id = n microtile: 8 rows
    const int n0   = blockIdx.x * TILE;

    // Init top-k state (key 0 can't collide with any real key).
    for (int i = tid; i < TILE * K_TOP; i += NTHREADS) lists[i] = 0ull;
    for (int i = tid; i < TILE; i += NTHREADS) thresh[i] = 0u;

    // Load this CTA's xb tile once, transposed: sB[k][n].
#pragma unroll
    for (int i = 0; i < 8; i++) {
        int idx = i * NTHREADS + tid;     // 0..4095 float4s
        int r   = idx >> 5;               // n row
        int c4  = (idx & 31) << 2;        // k 0,4,...,124
        float4 b = *(const float4*)(xb + (size_t)(n0 + r) * D_DIM + c4);
        sB[(c4 + 0) * SB_STRIDE + r] = b.x;
        sB[(c4 + 1) * SB_STRIDE + r] = b.y;
        sB[(c4 + 2) * SB_STRIDE + r] = b.z;
        sB[(c4 + 3) * SB_STRIDE + r] = b.w;
    }

    const int nTiles = Q / TILE;
    const int cTotal = nTiles * (D_DIM / KCH);

    // Prologue: chunks 0 and 1 in flight.
    load_chunk_async(sA,            xq, 0, 0,   tid);
    load_chunk_async(sA + SA_WORDS, xq, 0, KCH, tid);

    int ct = 0;
    for (int tile = 0; tile < nTiles; tile++) {
        const int q0 = tile * TILE;

        float acc[8][4];
#pragma unroll
        for (int i = 0; i < 8; i++)
#pragma unroll
            for (int j = 0; j < 4; j++) acc[i][j] = 0.f;

        for (int c = 0; c < D_DIM / KCH; c++, ct++) {
            // Wait for chunk ct (pending groups: ct issued .. ct+1).
            if (ct == cTotal - 1) {
                asm volatile("cp.async.wait_group 0;\n" ::: "memory");
            } else {
                asm volatile("cp.async.wait_group 1;\n" ::: "memory");
            }
            // Single barrier: publishes chunk ct to all warps AND proves all
            // warps finished reading the buffer that ct+2 will overwrite.
            __syncthreads();

            if (ct + 2 < cTotal) {
                int nct = ct + 2;
                load_chunk_async(sA + (nct % NSTAGE) * SA_WORDS, xq,
                                 (nct >> 2) * TILE, (nct & 3) * KCH, tid);
            }

            const float* A  = sA + (ct % NSTAGE) * SA_WORDS;
            const float* Bc = sB + c * KCH * SB_STRIDE;
#pragma unroll 8
            for (int k = 0; k < KCH; k++) {
                float a[4], bb[8];
                const float* Ak = A  + k * SA_STRIDE;
                const float* Bk = Bc + k * SB_STRIDE;
                // b: address depends only on warp id -> 32-lane broadcast.
                *(float4*)&bb[0] = *(const float4*)(Bk + ty * 8);
                *(float4*)&bb[4] = *(const float4*)(Bk + ty * 8 + 4);
                // a: lane-consecutive 16B -> conflict-free.
                *(float4*)&a[0]  = *(const float4*)(Ak + tx * 4);
#pragma unroll
                for (int i = 0; i < 8; i++)
#pragma unroll
                    for (int j = 0; j < 4; j++)
                        acc[i][j] = fmaf(bb[i], a[j], acc[i][j]);
            }
        }

        // ---------------- Top-k update (warp-private rows) ----------------
        // Warp ty owns rows n0 + ty*8 .. +7; lane tx holds q = q0+tx*4+j.
#pragma unroll
        for (int i = 0; i < 8; i++) {
            int row = ty * 8 + i;
            unsigned th = thresh[row];
            unsigned ov[4];
            bool any = false;
#pragma unroll
            for (int j = 0; j < 4; j++) {
                ov[j] = fp32_ord(acc[i][j]);
                any |= (ov[j] >= th);
            }
            unsigned bal = __ballot_sync(0xffffffffu, any);
            while (bal) {
                int t = __ffs(bal) - 1;
                bal &= bal - 1;
                if (lane == t) {
                    unsigned long long* L = lists + (size_t)row * K_TOP;
#pragma unroll
                    for (int j = 0; j < 4; j++) {
                        unsigned long long key =
                            ((unsigned long long)ov[j] << 32) |
                            (unsigned long long)(0xFFFFFFFFu - (unsigned)(q0 + tx * 4 + j));
                        if (key > L[K_TOP - 1]) {
                            int p = K_TOP - 1;
                            while (p > 0 && L[p - 1] < key) { L[p] = L[p - 1]; p--; }
                            L[p] = key;
                        }
                    }
                    thresh[row] = (unsigned)(L[K_TOP - 1] >> 32);
                }
                __syncwarp();
            }
        }
    }

    __syncthreads();
    // Emit: out[k][n] as FLOAT32 values (0..4095 exactly representable),
    // lists sorted by (value desc, index asc) == lax.top_k order.
    for (int e = tid; e < TILE * K_TOP; e += NTHREADS) {
        int row = e / K_TOP;
        int k   = e % K_TOP;
        unsigned idx = 0xFFFFFFFFu -
            (unsigned)(lists[(size_t)row * K_TOP + k] & 0xFFFFFFFFull);
        out[(size_t)k * N + (n0 + row)] = (float)idx;
    }
}

// ---------------------------------------------------------------------------
// Launch. Inputs bound BY SIZE: N comes from out_size (out is [21, N]); the
// input with N*128 elements is xb (database), the other is xq (queries).
// ---------------------------------------------------------------------------
extern "C" void kernel_launch(void* const* d_in, const int* in_sizes, int n_in,
                              void* d_out, int out_size)
{
    float* out = (float*)d_out;

    const int N = out_size / K_TOP;
    const float* xq;
    const float* xb;
    int Q;

    if (in_sizes[0] == N * D_DIM && in_sizes[1] != N * D_DIM) {
        xb = (const float*)d_in[0];
        xq = (const float*)d_in[1];
        Q  = in_sizes[1] / D_DIM;
    } else {
        xq = (const float*)d_in[0];
        xb = (const float*)d_in[1];
        Q  = in_sizes[0] / D_DIM;
    }

    const int smem_bytes = SB_WORDS * 4 + NSTAGE * SA_WORDS * 4
                         + TILE * K_TOP * 8 + TILE * 4;   // ~137 KB
    cudaFuncSetAttribute(fused_gemm_topk_kernel,
                         cudaFuncAttributeMaxDynamicSharedMemorySize, smem_bytes);

    fused_gemm_topk_kernel<<<N / TILE, NTHREADS, smem_bytes>>>(xq, xb, Q, N, out);
}